// round 9
// baseline (speedup 1.0000x reference)
#include <cuda_runtime.h>
#include <cuda_bf16.h>
#include <math.h>
#include <stdint.h>

#define NEGV (-1e10f)
#define KSPAN 1024
#define KANT 50
#define GIDIM 512
#define HID 1000
#define MROWS (KSPAN*KANT)   // 51200
#define KA 1024              // gate GEMM K
#define KPA 1088             // MLP GEMM K: [gj(512) | gi*gj(512) | onehot(18) pad 64] -> 2176B aligned rows
#define NPAD 1024
#define NSLOTS 16

// ---------------- device scratch ----------------
__device__ __nv_bfloat16 d_gb[KSPAN*GIDIM];
__device__ __nv_bfloat16 d_gnb[KSPAN*GIDIM];
__device__ __nv_bfloat16 d_wcb[GIDIM*GIDIM];
__device__ __nv_bfloat16 d_projb[KSPAN*GIDIM];
__device__ float d_ant[KSPAN*KSPAN];
__device__ float d_bs[KSPAN*KANT];
__device__ int   d_bi[KSPAN*KANT];
__device__ __nv_bfloat16 d_A2[(size_t)MROWS*KPA];
__device__ __nv_bfloat16 d_B2t[(size_t)NPAD*KPA];     // [W1b | W1c | Vc rows | 0pad]
__device__ __nv_bfloat16 d_B1t[(size_t)NPAD*GIDIM];   // W1a^T
__device__ __nv_bfloat16 d_wft[(size_t)GIDIM*KA];
__device__ __nv_bfloat16 d_gateA[(size_t)KSPAN*KA];
__device__ float d_Vi[(size_t)KSPAN*NPAD];
__device__ float d_Vg[8*NPAD];
__device__ float d_w2p[NPAD];
__device__ float d_b1p[NPAD];
__device__ float d_part[(size_t)NSLOTS*MROWS];
__device__ float d_sa[MROWS];
__device__ float d_an[KSPAN*GIDIM];

// ---------------- helpers ----------------
__device__ __forceinline__ uint32_t smem_u32(const void* p){
    uint32_t a; asm("{ .reg .u64 t; cvta.to.shared.u64 t, %1; cvt.u32.u64 %0, t; }" : "=r"(a) : "l"(p));
    return a;
}
__device__ __forceinline__ void cpasync16(uint32_t dst, const void* src){
    asm volatile("cp.async.cg.shared.global [%0], [%1], 16;\n" :: "r"(dst), "l"(src) : "memory");
}

// ---------------- merged prep (called 3x with base offsets) ----------------
__global__ void prep_master(int base, const float* __restrict__ g, const float* __restrict__ coarseW,
                            const float* __restrict__ W1, const float* __restrict__ Wf,
                            const float* __restrict__ b1, const float* __restrict__ W2,
                            const float* __restrict__ dist_e, const float* __restrict__ genre_e,
                            const float* __restrict__ spk_e){
    int b = base + blockIdx.x, t = threadIdx.x;
    if (b < 2048){
        int i = b*256 + t; d_gb[i] = __float2bfloat16(g[i]);
    } else if (b < 3072){
        int i = (b-2048)*256 + t; d_wcb[i] = __float2bfloat16(coarseW[i]);
    } else if (b < 5120){
        int idx = (b-3072)*256 + t;          // over NPAD*512
        int n = idx >> 9, k = idx & 511;
        float a=0.f, bb=0.f, c=0.f;
        if (n < HID){
            a  = W1[(size_t)k*HID + n];
            bb = W1[(size_t)(512+k)*HID + n];
            c  = W1[(size_t)(1024+k)*HID + n];
        }
        d_B1t[(size_t)n*GIDIM + k] = __float2bfloat16(a);
        d_B2t[(size_t)n*KPA + k]       = __float2bfloat16(bb);
        d_B2t[(size_t)n*KPA + 512 + k] = __float2bfloat16(c);
    } else if (b < 5376){
        int idx = (b-5120)*256 + t;          // over NPAD*64
        int n = idx >> 6, c = idx & 63;
        float s = 0.f;
        if (c < 18 && n < HID){
            int bin = c>>1, lab = (c&1)+1;
            for (int k=0;k<20;k++) s += dist_e[bin*20+k]*W1[(size_t)(1536+k)*HID+n]
                                      + spk_e[lab*20+k]*W1[(size_t)(1576+k)*HID+n];
        }
        d_B2t[(size_t)n*KPA + 1024 + c] = __float2bfloat16(s);
    } else if (b < 7424){
        int idx = (b-5376)*256 + t;
        int n = idx >> 10, k = idx & 1023;
        d_wft[idx] = __float2bfloat16(Wf[(size_t)k*GIDIM + n]);
    } else if (b < 7428){
        int n = (b-7424)*256 + t;
        d_w2p[n] = (n<HID)? W2[n]:0.f; d_b1p[n] = (n<HID)? b1[n]:0.f;
    } else {
        int idx = (b-7428)*256 + t;          // over 8*1024
        int row = idx >> 10, n = idx & 1023;
        float s = 0.f;
        if (n < HID)
            for (int k=0;k<20;k++) s += genre_e[row*20+k]*W1[(size_t)(1556+k)*HID+n];
        d_Vg[row*NPAD+n] = s;
    }
}

// ---------------- bf16 mma.sync GEMM (128x128), modes ----------------
// 0: proj->d_projb | 1: ant+mask | 2: Vi=acc+b1+Vg | 3: gate->d_gnb
// 6: fused proj (x<4) + Vi (x>=4), A=d_gb, K=512
__global__ void __launch_bounds__(256,2) bgemm(int mode, const __nv_bfloat16* __restrict__ A,
        const __nv_bfloat16* __restrict__ B, int Kdim,
        const float* __restrict__ aux0, const float* __restrict__ aux1,
        const int* __restrict__ auxi){
    __shared__ unsigned int sA[2][128*20];
    __shared__ unsigned int sB[2][128*20];
    int bx = blockIdx.x;
    const __nv_bfloat16* Bp = B;
    bool m6proj = false;
    int n0;
    if (mode == 6){
        m6proj = (bx < 4);
        Bp = m6proj ? d_wcb : d_B1t;
        n0 = (m6proj ? bx : bx-4)*128;
    } else n0 = bx*128;
    int m0 = blockIdx.y*128;
    int tid = threadIdx.x, lane = tid&31, warp = tid>>5;
    int wm = warp&3, wn = warp>>2;
    float acc[2][8][4];
    #pragma unroll
    for (int a=0;a<2;a++)
        #pragma unroll
        for (int b=0;b<8;b++)
            #pragma unroll
            for (int c=0;c<4;c++) acc[a][b][c]=0.f;
    auto issue = [&](int buf, int kt){
        int k0 = kt*32;
        #pragma unroll
        for (int it=0; it<2; it++){
            int e = tid + it*256, r = e>>2, c = e&3;
            cpasync16(smem_u32(&sA[buf][r*20+c*4]), A + (size_t)(m0+r)*Kdim + k0 + c*8);
            cpasync16(smem_u32(&sB[buf][r*20+c*4]), Bp + (size_t)(n0+r)*Kdim + k0 + c*8);
        }
        asm volatile("cp.async.commit_group;\n" ::: "memory");
    };
    issue(0,0);
    int KT = Kdim/32;
    for (int kt=0; kt<KT; kt++){
        int buf = kt&1;
        if (kt+1<KT){ issue(buf^1, kt+1); asm volatile("cp.async.wait_group 1;\n" ::: "memory"); }
        else asm volatile("cp.async.wait_group 0;\n" ::: "memory");
        __syncthreads();
        #pragma unroll
        for (int ks=0; ks<2; ks++){
            unsigned int af[2][4], bfr[8][2];
            int arow = wm*32 + (lane>>2), aw = ks*8 + (lane&3);
            #pragma unroll
            for (int mi=0;mi<2;mi++){
                int base = (arow+mi*16)*20;
                af[mi][0]=sA[buf][base+aw]; af[mi][1]=sA[buf][base+160+aw];
                af[mi][2]=sA[buf][base+aw+4]; af[mi][3]=sA[buf][base+160+aw+4];
            }
            int bb = wn*64 + (lane>>2);
            #pragma unroll
            for (int ni=0;ni<8;ni++){
                int base = (bb+ni*8)*20 + aw;
                bfr[ni][0]=sB[buf][base]; bfr[ni][1]=sB[buf][base+4];
            }
            #pragma unroll
            for (int mi=0;mi<2;mi++)
                #pragma unroll
                for (int ni=0;ni<8;ni++)
                    asm volatile("mma.sync.aligned.m16n8k16.row.col.f32.bf16.bf16.f32 "
                        "{%0,%1,%2,%3},{%4,%5,%6,%7},{%8,%9},{%0,%1,%2,%3};\n"
                        : "+f"(acc[mi][ni][0]), "+f"(acc[mi][ni][1]),
                          "+f"(acc[mi][ni][2]), "+f"(acc[mi][ni][3])
                        : "r"(af[mi][0]), "r"(af[mi][1]), "r"(af[mi][2]), "r"(af[mi][3]),
                          "r"(bfr[ni][0]), "r"(bfr[ni][1]));
        }
        __syncthreads();
    }
    #pragma unroll
    for (int mi=0;mi<2;mi++)
        #pragma unroll
        for (int ni=0;ni<8;ni++)
            #pragma unroll
            for (int q=0;q<4;q++){
                int m = m0 + wm*32 + mi*16 + (lane>>2) + ((q>=2)?8:0);
                int n = n0 + wn*64 + ni*8 + (lane&3)*2 + (q&1);
                float v = acc[mi][ni][q];
                if (mode==0 || (mode==6 && m6proj)) d_projb[(size_t)m*GIDIM+n] = __float2bfloat16(v);
                else if (mode==1){
                    v += aux0[m] + aux0[n];
                    if (n >= m) v += NEGV;
                    d_ant[(size_t)m*KSPAN+n] = v;
                } else if (mode==2 || mode==6){
                    d_Vi[(size_t)m*NPAD+n] = v + d_b1p[n] + d_Vg[auxi[m]*NPAD+n];
                } else {
                    float f = 1.f/(1.f+expf(-(v+aux0[n])));
                    float gv = aux1[(size_t)m*GIDIM+n];
                    float av = d_an[(size_t)m*GIDIM+n];
                    float o = (m==0)? gv : f*gv + (1.f-f)*av;
                    d_gnb[(size_t)m*GIDIM+n] = __float2bfloat16(o);
                }
            }
}

// ---------------- top-K bitonic ----------------
__global__ void topk_kernel(){
    int row = blockIdx.x;
    __shared__ unsigned long long sk[1024];
    for (int j=threadIdx.x; j<1024; j+=512){
        unsigned int b = __float_as_uint(d_ant[(size_t)row*KSPAN+j]);
        unsigned int asc = (b & 0x80000000u) ? ~b : (b | 0x80000000u);
        sk[j] = (((unsigned long long)(~asc))<<32) | (unsigned int)j;
    }
    __syncthreads();
    for (int k=2;k<=1024;k<<=1)
        for (int j=k>>1;j>0;j>>=1){
            for (int i=threadIdx.x;i<1024;i+=512){
                int ixj = i^j;
                if (ixj>i){
                    bool up = ((i&k)==0);
                    unsigned long long a=sk[i], b=sk[ixj];
                    if ((a>b)==up){ sk[i]=b; sk[ixj]=a; }
                }
            }
            __syncthreads();
        }
    if (threadIdx.x < KANT){
        int j = (int)(sk[threadIdx.x] & 0xffffffffu);
        d_bi[row*KANT+threadIdx.x] = j;
        d_bs[row*KANT+threadIdx.x] = d_ant[(size_t)row*KSPAN+j];
    }
}

// ---------------- build A2 = [gj | gi*gj | onehot18 | 0pad] ----------------
__global__ void build_A(int it, const int* __restrict__ starts, const int* __restrict__ ends,
                        const int* __restrict__ sids){
    const __nv_bfloat16* g = it ? d_gnb : d_gb;
    int warp = threadIdx.x>>5, lane = threadIdx.x&31;
    int r = blockIdx.x*8 + warp;
    int i = r/KANT, j = d_bi[r];
    const uint4* gi4 = (const uint4*)(g + (size_t)i*GIDIM);
    const uint4* gj4 = (const uint4*)(g + (size_t)j*GIDIM);
    uint4 a0 = gi4[lane*2], a1 = gi4[lane*2+1];
    uint4 b0 = gj4[lane*2], b1 = gj4[lane*2+1];
    uint4 p0, p1;
    {
        const __nv_bfloat162* ap = (const __nv_bfloat162*)&a0;
        const __nv_bfloat162* bp = (const __nv_bfloat162*)&b0;
        __nv_bfloat162* pp = (__nv_bfloat162*)&p0;
        #pragma unroll
        for (int w=0; w<4; w++) pp[w] = __hmul2(ap[w], bp[w]);
        ap = (const __nv_bfloat162*)&a1; bp = (const __nv_bfloat162*)&b1;
        pp = (__nv_bfloat162*)&p1;
        #pragma unroll
        for (int w=0; w<4; w++) pp[w] = __hmul2(ap[w], bp[w]);
    }
    __nv_bfloat16* Ar = d_A2 + (size_t)r*KPA;
    ((uint4*)Ar)[lane*2]   = b0;
    ((uint4*)Ar)[lane*2+1] = b1;
    ((uint4*)(Ar+512))[lane*2]   = p0;
    ((uint4*)(Ar+512))[lane*2+1] = p1;
    if (lane < 8){
        int d = ends[i]-starts[j];
        int bin = (d>1)+(d>2)+(d>3)+(d>4)+(d>8)+(d>16)+(d>32)+(d>64);
        int lab = (sids[i]==sids[j]) ? 1 : 2;
        int meta = bin*2 + lab - 1;        // 0..17
        uint4 z = make_uint4(0,0,0,0);
        int dd = meta - lane*8;
        if (dd >= 0 && dd < 8){
            unsigned int val = 0x3F80u << (16*(dd&1));
            ((unsigned int*)&z)[dd>>1] = val;
        }
        ((uint4*)(Ar+1024))[lane] = z;     // covers cols 1024..1087
    }
}

// ---------------- MLP GEMM (K=1088) + fused relu*W2 epilogue ----------------
__global__ void __launch_bounds__(256,2) mlp_bf(){
    __shared__ unsigned int sA[2][128*20];
    __shared__ unsigned int sB[2][128*20];
    __shared__ float sVi[4*132];
    __shared__ float sW2[128];
    __shared__ unsigned char iIdx[128];
    int nt = blockIdx.x, n0 = nt*128, m0 = blockIdx.y*128;
    int tid = threadIdx.x, lane = tid&31, warp = tid>>5;
    int wm = warp&3, wn = warp>>2;
    int i0 = m0/KANT;
    if (tid < 128){
        iIdx[tid] = (unsigned char)((m0+tid)/KANT - i0);
        sW2[tid] = d_w2p[n0+tid];
    }
    {
        int rr = tid>>6, cc = tid&63;
        int row = min(i0+rr, KSPAN-1);
        *(float2*)(sVi + rr*132 + cc*2) = *(const float2*)(d_Vi + (size_t)row*NPAD + n0 + cc*2);
    }
    float acc[2][8][4];
    #pragma unroll
    for (int a=0;a<2;a++)
        #pragma unroll
        for (int b=0;b<8;b++)
            #pragma unroll
            for (int c=0;c<4;c++) acc[a][b][c]=0.f;
    auto issue = [&](int buf, int kt){
        int k0 = kt*32;
        #pragma unroll
        for (int it=0; it<2; it++){
            int e = tid + it*256, r = e>>2, c = e&3;
            cpasync16(smem_u32(&sA[buf][r*20+c*4]), d_A2  + (size_t)(m0+r)*KPA + k0 + c*8);
            cpasync16(smem_u32(&sB[buf][r*20+c*4]), d_B2t + (size_t)(n0+r)*KPA + k0 + c*8);
        }
        asm volatile("cp.async.commit_group;\n" ::: "memory");
    };
    issue(0,0);
    const int KT = KPA/32;   // 34
    for (int kt=0; kt<KT; kt++){
        int buf = kt&1;
        if (kt+1<KT){ issue(buf^1, kt+1); asm volatile("cp.async.wait_group 1;\n" ::: "memory"); }
        else asm volatile("cp.async.wait_group 0;\n" ::: "memory");
        __syncthreads();
        #pragma unroll
        for (int ks=0; ks<2; ks++){
            unsigned int af[2][4], bfr[8][2];
            int arow = wm*32 + (lane>>2), aw = ks*8 + (lane&3);
            #pragma unroll
            for (int mi=0;mi<2;mi++){
                int base = (arow+mi*16)*20;
                af[mi][0]=sA[buf][base+aw]; af[mi][1]=sA[buf][base+160+aw];
                af[mi][2]=sA[buf][base+aw+4]; af[mi][3]=sA[buf][base+160+aw+4];
            }
            int bb = wn*64 + (lane>>2);
            #pragma unroll
            for (int ni=0;ni<8;ni++){
                int base = (bb+ni*8)*20 + aw;
                bfr[ni][0]=sB[buf][base]; bfr[ni][1]=sB[buf][base+4];
            }
            #pragma unroll
            for (int mi=0;mi<2;mi++)
                #pragma unroll
                for (int ni=0;ni<8;ni++)
                    asm volatile("mma.sync.aligned.m16n8k16.row.col.f32.bf16.bf16.f32 "
                        "{%0,%1,%2,%3},{%4,%5,%6,%7},{%8,%9},{%0,%1,%2,%3};\n"
                        : "+f"(acc[mi][ni][0]), "+f"(acc[mi][ni][1]),
                          "+f"(acc[mi][ni][2]), "+f"(acc[mi][ni][3])
                        : "r"(af[mi][0]), "r"(af[mi][1]), "r"(af[mi][2]), "r"(af[mi][3]),
                          "r"(bfr[ni][0]), "r"(bfr[ni][1]));
        }
        __syncthreads();
    }
    // epilogue: h = acc + Vi(smem); rs += relu(h)*w2(smem)
    int slot = nt*2 + wn;
    #pragma unroll
    for (int mi=0;mi<2;mi++){
        int rA = wm*32 + mi*16 + (lane>>2), rB = rA+8;
        const float* viA = sVi + iIdx[rA]*132;
        const float* viB = sVi + iIdx[rB]*132;
        float rs0 = 0.f, rs1 = 0.f;
        #pragma unroll
        for (int ni=0;ni<8;ni++){
            int nl = wn*64 + ni*8 + (lane&3)*2;
            float2 wv = *(const float2*)(sW2 + nl);
            float2 va = *(const float2*)(viA + nl);
            float2 vb = *(const float2*)(viB + nl);
            rs0 += fmaxf(acc[mi][ni][0]+va.x, 0.f)*wv.x + fmaxf(acc[mi][ni][1]+va.y, 0.f)*wv.y;
            rs1 += fmaxf(acc[mi][ni][2]+vb.x, 0.f)*wv.x + fmaxf(acc[mi][ni][3]+vb.y, 0.f)*wv.y;
        }
        rs0 += __shfl_xor_sync(0xffffffffu, rs0, 1);
        rs0 += __shfl_xor_sync(0xffffffffu, rs0, 2);
        rs1 += __shfl_xor_sync(0xffffffffu, rs1, 1);
        rs1 += __shfl_xor_sync(0xffffffffu, rs1, 2);
        if ((lane&3)==0){
            d_part[(size_t)slot*MROWS + m0 + rA] = rs0;
            d_part[(size_t)slot*MROWS + m0 + rB] = rs1;
        }
    }
}

__global__ void reduce_sa(){
    int m = blockIdx.x*256 + threadIdx.x;
    if (m >= MROWS) return;
    float s = 0.f;
    #pragma unroll
    for (int t=0; t<NSLOTS; t++) s += d_part[(size_t)t*MROWS + m];
    d_sa[m] = s;
}

// ---------------- refinement ----------------
__global__ void refine_kernel(const float* __restrict__ g, const float* __restrict__ b2){
    int i = blockIdx.x;
    int nv = min(i, KANT);
    __shared__ float p[KANT+1];
    __shared__ int ji[KANT];
    __shared__ float red[128];
    int tid = threadIdx.x;
    float val;
    if (tid==0) val = 0.f;
    else if (tid<=KANT){
        int kk = tid-1;
        val = (kk<nv) ? d_sa[i*KANT+kk] + b2[0] + d_bs[i*KANT+kk] : NEGV;
    } else val = NEGV;
    red[tid]=val; __syncthreads();
    for (int s=64;s>0;s>>=1){ if (tid<s) red[tid]=fmaxf(red[tid],red[tid+s]); __syncthreads(); }
    float mx = red[0]; __syncthreads();
    float e = (tid<=KANT) ? expf(val-mx) : 0.f;
    red[tid]=e; __syncthreads();
    for (int s=64;s>0;s>>=1){ if (tid<s) red[tid]+=red[tid+s]; __syncthreads(); }
    float sum = red[0];
    if (tid<=KANT) p[tid] = e/sum;
    if (tid<KANT) ji[tid] = d_bi[i*KANT+tid];
    __syncthreads();
    for (int d=tid; d<GIDIM; d+=128){
        float a = p[0]*g[(size_t)i*GIDIM+d];
        for (int kk=0;kk<nv;kk++) a += p[kk+1]*g[(size_t)ji[kk]*GIDIM+d];
        d_an[(size_t)i*GIDIM+d] = a;
    }
}

__global__ void build_gateA(const float* __restrict__ g){
    int idx = blockIdx.x*256 + threadIdx.x;
    if (idx >= KSPAN*GIDIM) return;
    int m = idx/GIDIM, d = idx - m*GIDIM;
    d_gateA[(size_t)m*KA + d]         = __float2bfloat16(g[idx]);
    d_gateA[(size_t)m*KA + GIDIM + d] = __float2bfloat16(d_an[idx]);
}

__global__ void final_kernel(const float* __restrict__ b2, float* __restrict__ out){
    int idx = blockIdx.x*256 + threadIdx.x;
    if (idx >= KSPAN*(KANT+1)) return;
    int i = idx/(KANT+1), c = idx - i*(KANT+1);
    float v;
    if (c==0) v = 0.f;
    else {
        int kk = c-1;
        if (i==0) v = (kk==0)? 0.f : NEGV;
        else      v = (kk < min(i,KANT)) ? d_sa[i*KANT+kk] + b2[0] + d_bs[i*KANT+kk] : NEGV;
    }
    out[idx] = v;
}

// ---------------- launch ----------------
extern "C" void kernel_launch(void* const* d_in, const int* in_sizes, int n_in,
                              void* d_out, int out_size){
    const float* g_i     = (const float*)d_in[0];
    const float* mention = (const float*)d_in[1];
    const float* dist_e  = (const float*)d_in[2];
    const float* genre_e = (const float*)d_in[3];
    const float* spk_e   = (const float*)d_in[4];
    const float* coarseW = (const float*)d_in[5];
    const float* W1      = (const float*)d_in[6];
    const float* b1      = (const float*)d_in[7];
    const float* W2      = (const float*)d_in[8];
    const float* b2      = (const float*)d_in[9];
    const float* Wf      = (const float*)d_in[10];
    const float* bfv     = (const float*)d_in[11];
    const int* starts    = (const int*)d_in[12];
    const int* ends      = (const int*)d_in[13];
    const int* gids      = (const int*)d_in[14];
    const int* sids      = (const int*)d_in[15];
    float* out = (float*)d_out;

    // prep split into 3 so that user launch #4 (profiled by ncu -s 5) is the mode-6 bgemm
    prep_master<<<3072,256>>>(0,    g_i, coarseW, W1, Wf, b1, W2, dist_e, genre_e, spk_e); // 1
    prep_master<<<2304,256>>>(3072, g_i, coarseW, W1, Wf, b1, W2, dist_e, genre_e, spk_e); // 2
    prep_master<<<2084,256>>>(5376, g_i, coarseW, W1, Wf, b1, W2, dist_e, genre_e, spk_e); // 3
    bgemm<<<dim3(12, KSPAN/128),256>>>(6, d_gb, nullptr, GIDIM, nullptr, nullptr, gids);   // 4 <- profiled
    bgemm<<<dim3(KSPAN/128, KSPAN/128),256>>>(1, d_projb, d_gb, GIDIM, mention, nullptr, nullptr); // 5
    topk_kernel<<<KSPAN,512>>>();                                                          // 6
    build_A<<<MROWS/8,256>>>(0, starts, ends, sids);                                       // 7
    mlp_bf<<<dim3(NPAD/128, MROWS/128),256>>>();                                           // 8
    reduce_sa<<<(MROWS+255)/256,256>>>();
    refine_kernel<<<KSPAN,128>>>(g_i, b2);
    build_gateA<<<(KSPAN*GIDIM+255)/256,256>>>(g_i);
    bgemm<<<dim3(GIDIM/128, KSPAN/128),256>>>(3, d_gateA, d_wft, KA, bfv, g_i, nullptr);
    // iteration 1
    bgemm<<<dim3(NPAD/128, KSPAN/128),256>>>(2, d_gnb, d_B1t, GIDIM, nullptr, nullptr, gids);
    build_A<<<MROWS/8,256>>>(1, starts, ends, sids);
    mlp_bf<<<dim3(NPAD/128, MROWS/128),256>>>();
    reduce_sa<<<(MROWS+255)/256,256>>>();
    final_kernel<<<(KSPAN*(KANT+1)+255)/256,256>>>(b2, out);
}

// round 10
// speedup vs baseline: 1.0164x; 1.0164x over previous
#include <cuda_runtime.h>
#include <cuda_bf16.h>
#include <math.h>
#include <stdint.h>

#define NEGV (-1e10f)
#define KSPAN 1024
#define KANT 50
#define GIDIM 512
#define HID 1000
#define MROWS (KSPAN*KANT)   // 51200
#define KA 1024              // gate GEMM K
#define KPA 1088             // MLP GEMM K: [gj(512) | gi*gj(512) | onehot(18) pad 64]
#define NPAD 1024
#define NSLOTS 16

#define BG_SMEM 81920        // 4 stages x (A 10240B + B 10240B)
#define MLP_SMEM 84672       // + sVi(2112) + sW2(512) + iIdx(128)

// ---------------- device scratch ----------------
__device__ __nv_bfloat16 d_gb[KSPAN*GIDIM];
__device__ __nv_bfloat16 d_gnb[KSPAN*GIDIM];
__device__ __nv_bfloat16 d_wcb[GIDIM*GIDIM];
__device__ __nv_bfloat16 d_projb[KSPAN*GIDIM];
__device__ float d_ant[KSPAN*KSPAN];
__device__ float d_bs[KSPAN*KANT];
__device__ int   d_bi[KSPAN*KANT];
__device__ __nv_bfloat16 d_A2[(size_t)MROWS*KPA];
__device__ __nv_bfloat16 d_B2t[(size_t)NPAD*KPA];     // [W1b | W1c | Vc rows | 0pad]
__device__ __nv_bfloat16 d_B1t[(size_t)NPAD*GIDIM];   // W1a^T
__device__ __nv_bfloat16 d_wft[(size_t)GIDIM*KA];
__device__ __nv_bfloat16 d_gateA[(size_t)KSPAN*KA];
__device__ float d_Vi[(size_t)KSPAN*NPAD];
__device__ float d_Vg[8*NPAD];
__device__ float d_w2p[NPAD];
__device__ float d_b1p[NPAD];
__device__ float d_part[(size_t)NSLOTS*MROWS];
__device__ float d_sa[MROWS];
__device__ float d_an[KSPAN*GIDIM];

// ---------------- helpers ----------------
__device__ __forceinline__ uint32_t smem_u32(const void* p){
    uint32_t a; asm("{ .reg .u64 t; cvta.to.shared.u64 t, %1; cvt.u32.u64 %0, t; }" : "=r"(a) : "l"(p));
    return a;
}
__device__ __forceinline__ void cpasync16(uint32_t dst, const void* src){
    asm volatile("cp.async.cg.shared.global [%0], [%1], 16;\n" :: "r"(dst), "l"(src) : "memory");
}
#define WG(n) asm volatile("cp.async.wait_group %0;\n" :: "n"(n) : "memory")
#define CommitG() asm volatile("cp.async.commit_group;\n" ::: "memory")

// ---------------- merged prep (called 3x with base offsets) ----------------
__global__ void prep_master(int base, const float* __restrict__ g, const float* __restrict__ coarseW,
                            const float* __restrict__ W1, const float* __restrict__ Wf,
                            const float* __restrict__ b1, const float* __restrict__ W2,
                            const float* __restrict__ dist_e, const float* __restrict__ genre_e,
                            const float* __restrict__ spk_e){
    int b = base + blockIdx.x, t = threadIdx.x;
    if (b < 2048){
        int i = b*256 + t; d_gb[i] = __float2bfloat16(g[i]);
    } else if (b < 3072){
        int i = (b-2048)*256 + t; d_wcb[i] = __float2bfloat16(coarseW[i]);
    } else if (b < 5120){
        int idx = (b-3072)*256 + t;          // over NPAD*512
        int n = idx >> 9, k = idx & 511;
        float a=0.f, bb=0.f, c=0.f;
        if (n < HID){
            a  = W1[(size_t)k*HID + n];
            bb = W1[(size_t)(512+k)*HID + n];
            c  = W1[(size_t)(1024+k)*HID + n];
        }
        d_B1t[(size_t)n*GIDIM + k] = __float2bfloat16(a);
        d_B2t[(size_t)n*KPA + k]       = __float2bfloat16(bb);
        d_B2t[(size_t)n*KPA + 512 + k] = __float2bfloat16(c);
    } else if (b < 5376){
        int idx = (b-5120)*256 + t;          // over NPAD*64
        int n = idx >> 6, c = idx & 63;
        float s = 0.f;
        if (c < 18 && n < HID){
            int bin = c>>1, lab = (c&1)+1;
            for (int k=0;k<20;k++) s += dist_e[bin*20+k]*W1[(size_t)(1536+k)*HID+n]
                                      + spk_e[lab*20+k]*W1[(size_t)(1576+k)*HID+n];
        }
        d_B2t[(size_t)n*KPA + 1024 + c] = __float2bfloat16(s);
    } else if (b < 7424){
        int idx = (b-5376)*256 + t;
        int n = idx >> 10, k = idx & 1023;
        d_wft[idx] = __float2bfloat16(Wf[(size_t)k*GIDIM + n]);
    } else if (b < 7428){
        int n = (b-7424)*256 + t;
        d_w2p[n] = (n<HID)? W2[n]:0.f; d_b1p[n] = (n<HID)? b1[n]:0.f;
    } else {
        int idx = (b-7428)*256 + t;          // over 8*1024
        int row = idx >> 10, n = idx & 1023;
        float s = 0.f;
        if (n < HID)
            for (int k=0;k<20;k++) s += genre_e[row*20+k]*W1[(size_t)(1556+k)*HID+n];
        d_Vg[row*NPAD+n] = s;
    }
}

// ---------------- bf16 mma.sync GEMM (128x128), 4-stage pipeline ----------------
// 0: proj->d_projb | 1: ant+mask | 2: Vi=acc+b1+Vg | 3: gate->d_gnb
// 6: fused proj (x<4) + Vi (x>=4), A=d_gb, K=512
__global__ void __launch_bounds__(256,2) bgemm(int mode, const __nv_bfloat16* __restrict__ A,
        const __nv_bfloat16* __restrict__ B, int Kdim,
        const float* __restrict__ aux0, const float* __restrict__ aux1,
        const int* __restrict__ auxi){
    extern __shared__ char dsm[];
    unsigned int* sw = (unsigned int*)dsm;   // stage s: A words [s*5120, +2560), B [+2560, +5120)
    int bx = blockIdx.x;
    const __nv_bfloat16* Bp = B;
    bool m6proj = false;
    int n0;
    if (mode == 6){
        m6proj = (bx < 4);
        Bp = m6proj ? d_wcb : d_B1t;
        n0 = (m6proj ? bx : bx-4)*128;
    } else n0 = bx*128;
    int m0 = blockIdx.y*128;
    int tid = threadIdx.x, lane = tid&31, warp = tid>>5;
    int wm = warp&3, wn = warp>>2;
    float acc[2][8][4];
    #pragma unroll
    for (int a=0;a<2;a++)
        #pragma unroll
        for (int b=0;b<8;b++)
            #pragma unroll
            for (int c=0;c<4;c++) acc[a][b][c]=0.f;
    int r0 = tid>>2, c4 = tid&3;
    auto issue = [&](int k){
        int st = k & 3;
        int k0 = k*32;
        #pragma unroll
        for (int it=0; it<2; it++){
            int r = r0 + it*64;
            uint32_t base = smem_u32(sw + st*5120 + r*20 + c4*4);
            cpasync16(base,                 A  + (size_t)(m0+r)*Kdim + k0 + c4*8);
            cpasync16(base + 2560*4,        Bp + (size_t)(n0+r)*Kdim + k0 + c4*8);
        }
        CommitG();
    };
    issue(0); issue(1); issue(2);
    int KT = Kdim/32;
    for (int kt=0; kt<KT; kt++){
        int st = kt & 3;
        if (kt+3 < KT){ issue(kt+3); WG(3); }
        else { int ah = KT-1-kt; if (ah==2) WG(2); else if (ah==1) WG(1); else WG(0); }
        __syncthreads();
        int wb = st*5120;
        #pragma unroll
        for (int ks=0; ks<2; ks++){
            unsigned int af[2][4], bfr[8][2];
            int arow = wm*32 + (lane>>2), aw = ks*8 + (lane&3);
            #pragma unroll
            for (int mi=0;mi<2;mi++){
                int base = wb + (arow+mi*16)*20;
                af[mi][0]=sw[base+aw]; af[mi][1]=sw[base+160+aw];
                af[mi][2]=sw[base+aw+4]; af[mi][3]=sw[base+160+aw+4];
            }
            int bb = wn*64 + (lane>>2);
            #pragma unroll
            for (int ni=0;ni<8;ni++){
                int base = wb + 2560 + (bb+ni*8)*20 + aw;
                bfr[ni][0]=sw[base]; bfr[ni][1]=sw[base+4];
            }
            #pragma unroll
            for (int mi=0;mi<2;mi++)
                #pragma unroll
                for (int ni=0;ni<8;ni++)
                    asm volatile("mma.sync.aligned.m16n8k16.row.col.f32.bf16.bf16.f32 "
                        "{%0,%1,%2,%3},{%4,%5,%6,%7},{%8,%9},{%0,%1,%2,%3};\n"
                        : "+f"(acc[mi][ni][0]), "+f"(acc[mi][ni][1]),
                          "+f"(acc[mi][ni][2]), "+f"(acc[mi][ni][3])
                        : "r"(af[mi][0]), "r"(af[mi][1]), "r"(af[mi][2]), "r"(af[mi][3]),
                          "r"(bfr[ni][0]), "r"(bfr[ni][1]));
        }
        __syncthreads();
    }
    #pragma unroll
    for (int mi=0;mi<2;mi++)
        #pragma unroll
        for (int ni=0;ni<8;ni++)
            #pragma unroll
            for (int q=0;q<4;q++){
                int m = m0 + wm*32 + mi*16 + (lane>>2) + ((q>=2)?8:0);
                int n = n0 + wn*64 + ni*8 + (lane&3)*2 + (q&1);
                float v = acc[mi][ni][q];
                if (mode==0 || (mode==6 && m6proj)) d_projb[(size_t)m*GIDIM+n] = __float2bfloat16(v);
                else if (mode==1){
                    v += aux0[m] + aux0[n];
                    if (n >= m) v += NEGV;
                    d_ant[(size_t)m*KSPAN+n] = v;
                } else if (mode==2 || mode==6){
                    d_Vi[(size_t)m*NPAD+n] = v + d_b1p[n] + d_Vg[auxi[m]*NPAD+n];
                } else {
                    float f = 1.f/(1.f+expf(-(v+aux0[n])));
                    float gv = aux1[(size_t)m*GIDIM+n];
                    float av = d_an[(size_t)m*GIDIM+n];
                    float o = (m==0)? gv : f*gv + (1.f-f)*av;
                    d_gnb[(size_t)m*GIDIM+n] = __float2bfloat16(o);
                }
            }
}

// ---------------- top-K bitonic ----------------
__global__ void topk_kernel(){
    int row = blockIdx.x;
    __shared__ unsigned long long sk[1024];
    for (int j=threadIdx.x; j<1024; j+=512){
        unsigned int b = __float_as_uint(d_ant[(size_t)row*KSPAN+j]);
        unsigned int asc = (b & 0x80000000u) ? ~b : (b | 0x80000000u);
        sk[j] = (((unsigned long long)(~asc))<<32) | (unsigned int)j;
    }
    __syncthreads();
    for (int k=2;k<=1024;k<<=1)
        for (int j=k>>1;j>0;j>>=1){
            for (int i=threadIdx.x;i<1024;i+=512){
                int ixj = i^j;
                if (ixj>i){
                    bool up = ((i&k)==0);
                    unsigned long long a=sk[i], b=sk[ixj];
                    if ((a>b)==up){ sk[i]=b; sk[ixj]=a; }
                }
            }
            __syncthreads();
        }
    if (threadIdx.x < KANT){
        int j = (int)(sk[threadIdx.x] & 0xffffffffu);
        d_bi[row*KANT+threadIdx.x] = j;
        d_bs[row*KANT+threadIdx.x] = d_ant[(size_t)row*KSPAN+j];
    }
}

// ---------------- build A2 = [gj | gi*gj | onehot18 | 0pad] ----------------
__global__ void build_A(int it, const int* __restrict__ starts, const int* __restrict__ ends,
                        const int* __restrict__ sids){
    const __nv_bfloat16* g = it ? d_gnb : d_gb;
    int warp = threadIdx.x>>5, lane = threadIdx.x&31;
    int r = blockIdx.x*8 + warp;
    int i = r/KANT, j = d_bi[r];
    const uint4* gi4 = (const uint4*)(g + (size_t)i*GIDIM);
    const uint4* gj4 = (const uint4*)(g + (size_t)j*GIDIM);
    uint4 a0 = gi4[lane*2], a1 = gi4[lane*2+1];
    uint4 b0 = gj4[lane*2], b1 = gj4[lane*2+1];
    uint4 p0, p1;
    {
        const __nv_bfloat162* ap = (const __nv_bfloat162*)&a0;
        const __nv_bfloat162* bp = (const __nv_bfloat162*)&b0;
        __nv_bfloat162* pp = (__nv_bfloat162*)&p0;
        #pragma unroll
        for (int w=0; w<4; w++) pp[w] = __hmul2(ap[w], bp[w]);
        ap = (const __nv_bfloat162*)&a1; bp = (const __nv_bfloat162*)&b1;
        pp = (__nv_bfloat162*)&p1;
        #pragma unroll
        for (int w=0; w<4; w++) pp[w] = __hmul2(ap[w], bp[w]);
    }
    __nv_bfloat16* Ar = d_A2 + (size_t)r*KPA;
    ((uint4*)Ar)[lane*2]   = b0;
    ((uint4*)Ar)[lane*2+1] = b1;
    ((uint4*)(Ar+512))[lane*2]   = p0;
    ((uint4*)(Ar+512))[lane*2+1] = p1;
    if (lane < 8){
        int d = ends[i]-starts[j];
        int bin = (d>1)+(d>2)+(d>3)+(d>4)+(d>8)+(d>16)+(d>32)+(d>64);
        int lab = (sids[i]==sids[j]) ? 1 : 2;
        int meta = bin*2 + lab - 1;        // 0..17
        uint4 z = make_uint4(0,0,0,0);
        int dd = meta - lane*8;
        if (dd >= 0 && dd < 8){
            unsigned int val = 0x3F80u << (16*(dd&1));
            ((unsigned int*)&z)[dd>>1] = val;
        }
        ((uint4*)(Ar+1024))[lane] = z;     // covers cols 1024..1087
    }
}

// ---------------- MLP GEMM (K=1088), 4-stage pipeline + fused relu*W2 epilogue ----------------
__global__ void __launch_bounds__(256,2) mlp_bf(){
    extern __shared__ char dsm[];
    unsigned int* sw = (unsigned int*)dsm;
    float* sVi = (float*)(dsm + 81920);
    float* sW2 = (float*)(dsm + 84032);
    unsigned char* iIdx = (unsigned char*)(dsm + 84544);
    int nt = blockIdx.x, n0 = nt*128, m0 = blockIdx.y*128;
    int tid = threadIdx.x, lane = tid&31, warp = tid>>5;
    int wm = warp&3, wn = warp>>2;
    int i0 = m0/KANT;
    if (tid < 128){
        iIdx[tid] = (unsigned char)((m0+tid)/KANT - i0);
        sW2[tid] = d_w2p[n0+tid];
    }
    {
        int rr = tid>>6, cc = tid&63;
        int row = min(i0+rr, KSPAN-1);
        *(float2*)(sVi + rr*132 + cc*2) = *(const float2*)(d_Vi + (size_t)row*NPAD + n0 + cc*2);
    }
    float acc[2][8][4];
    #pragma unroll
    for (int a=0;a<2;a++)
        #pragma unroll
        for (int b=0;b<8;b++)
            #pragma unroll
            for (int c=0;c<4;c++) acc[a][b][c]=0.f;
    int r0 = tid>>2, c4 = tid&3;
    auto issue = [&](int k){
        int st = k & 3;
        int k0 = k*32;
        #pragma unroll
        for (int it=0; it<2; it++){
            int r = r0 + it*64;
            uint32_t base = smem_u32(sw + st*5120 + r*20 + c4*4);
            cpasync16(base,          d_A2  + (size_t)(m0+r)*KPA + k0 + c4*8);
            cpasync16(base + 2560*4, d_B2t + (size_t)(n0+r)*KPA + k0 + c4*8);
        }
        CommitG();
    };
    issue(0); issue(1); issue(2);
    const int KT = KPA/32;   // 34
    for (int kt=0; kt<KT; kt++){
        int st = kt & 3;
        if (kt+3 < KT){ issue(kt+3); WG(3); }
        else { int ah = KT-1-kt; if (ah==2) WG(2); else if (ah==1) WG(1); else WG(0); }
        __syncthreads();
        int wb = st*5120;
        #pragma unroll
        for (int ks=0; ks<2; ks++){
            unsigned int af[2][4], bfr[8][2];
            int arow = wm*32 + (lane>>2), aw = ks*8 + (lane&3);
            #pragma unroll
            for (int mi=0;mi<2;mi++){
                int base = wb + (arow+mi*16)*20;
                af[mi][0]=sw[base+aw]; af[mi][1]=sw[base+160+aw];
                af[mi][2]=sw[base+aw+4]; af[mi][3]=sw[base+160+aw+4];
            }
            int bb = wn*64 + (lane>>2);
            #pragma unroll
            for (int ni=0;ni<8;ni++){
                int base = wb + 2560 + (bb+ni*8)*20 + aw;
                bfr[ni][0]=sw[base]; bfr[ni][1]=sw[base+4];
            }
            #pragma unroll
            for (int mi=0;mi<2;mi++)
                #pragma unroll
                for (int ni=0;ni<8;ni++)
                    asm volatile("mma.sync.aligned.m16n8k16.row.col.f32.bf16.bf16.f32 "
                        "{%0,%1,%2,%3},{%4,%5,%6,%7},{%8,%9},{%0,%1,%2,%3};\n"
                        : "+f"(acc[mi][ni][0]), "+f"(acc[mi][ni][1]),
                          "+f"(acc[mi][ni][2]), "+f"(acc[mi][ni][3])
                        : "r"(af[mi][0]), "r"(af[mi][1]), "r"(af[mi][2]), "r"(af[mi][3]),
                          "r"(bfr[ni][0]), "r"(bfr[ni][1]));
        }
        __syncthreads();
    }
    // epilogue: h = acc + Vi(smem); rs += relu(h)*w2(smem)
    int slot = nt*2 + wn;
    #pragma unroll
    for (int mi=0;mi<2;mi++){
        int rA = wm*32 + mi*16 + (lane>>2), rB = rA+8;
        const float* viA = sVi + iIdx[rA]*132;
        const float* viB = sVi + iIdx[rB]*132;
        float rs0 = 0.f, rs1 = 0.f;
        #pragma unroll
        for (int ni=0;ni<8;ni++){
            int nl = wn*64 + ni*8 + (lane&3)*2;
            float2 wv = *(const float2*)(sW2 + nl);
            float2 va = *(const float2*)(viA + nl);
            float2 vb = *(const float2*)(viB + nl);
            rs0 += fmaxf(acc[mi][ni][0]+va.x, 0.f)*wv.x + fmaxf(acc[mi][ni][1]+va.y, 0.f)*wv.y;
            rs1 += fmaxf(acc[mi][ni][2]+vb.x, 0.f)*wv.x + fmaxf(acc[mi][ni][3]+vb.y, 0.f)*wv.y;
        }
        rs0 += __shfl_xor_sync(0xffffffffu, rs0, 1);
        rs0 += __shfl_xor_sync(0xffffffffu, rs0, 2);
        rs1 += __shfl_xor_sync(0xffffffffu, rs1, 1);
        rs1 += __shfl_xor_sync(0xffffffffu, rs1, 2);
        if ((lane&3)==0){
            d_part[(size_t)slot*MROWS + m0 + rA] = rs0;
            d_part[(size_t)slot*MROWS + m0 + rB] = rs1;
        }
    }
}

__global__ void reduce_sa(){
    int m = blockIdx.x*256 + threadIdx.x;
    if (m >= MROWS) return;
    float s = 0.f;
    #pragma unroll
    for (int t=0; t<NSLOTS; t++) s += d_part[(size_t)t*MROWS + m];
    d_sa[m] = s;
}

// ---------------- refinement ----------------
__global__ void refine_kernel(const float* __restrict__ g, const float* __restrict__ b2){
    int i = blockIdx.x;
    int nv = min(i, KANT);
    __shared__ float p[KANT+1];
    __shared__ int ji[KANT];
    __shared__ float red[128];
    int tid = threadIdx.x;
    float val;
    if (tid==0) val = 0.f;
    else if (tid<=KANT){
        int kk = tid-1;
        val = (kk<nv) ? d_sa[i*KANT+kk] + b2[0] + d_bs[i*KANT+kk] : NEGV;
    } else val = NEGV;
    red[tid]=val; __syncthreads();
    for (int s=64;s>0;s>>=1){ if (tid<s) red[tid]=fmaxf(red[tid],red[tid+s]); __syncthreads(); }
    float mx = red[0]; __syncthreads();
    float e = (tid<=KANT) ? expf(val-mx) : 0.f;
    red[tid]=e; __syncthreads();
    for (int s=64;s>0;s>>=1){ if (tid<s) red[tid]+=red[tid+s]; __syncthreads(); }
    float sum = red[0];
    if (tid<=KANT) p[tid] = e/sum;
    if (tid<KANT) ji[tid] = d_bi[i*KANT+tid];
    __syncthreads();
    for (int d=tid; d<GIDIM; d+=128){
        float a = p[0]*g[(size_t)i*GIDIM+d];
        for (int kk=0;kk<nv;kk++) a += p[kk+1]*g[(size_t)ji[kk]*GIDIM+d];
        d_an[(size_t)i*GIDIM+d] = a;
    }
}

__global__ void build_gateA(const float* __restrict__ g){
    int idx = blockIdx.x*256 + threadIdx.x;
    if (idx >= KSPAN*GIDIM) return;
    int m = idx/GIDIM, d = idx - m*GIDIM;
    d_gateA[(size_t)m*KA + d]         = __float2bfloat16(g[idx]);
    d_gateA[(size_t)m*KA + GIDIM + d] = __float2bfloat16(d_an[idx]);
}

__global__ void final_kernel(const float* __restrict__ b2, float* __restrict__ out){
    int idx = blockIdx.x*256 + threadIdx.x;
    if (idx >= KSPAN*(KANT+1)) return;
    int i = idx/(KANT+1), c = idx - i*(KANT+1);
    float v;
    if (c==0) v = 0.f;
    else {
        int kk = c-1;
        if (i==0) v = (kk==0)? 0.f : NEGV;
        else      v = (kk < min(i,KANT)) ? d_sa[i*KANT+kk] + b2[0] + d_bs[i*KANT+kk] : NEGV;
    }
    out[idx] = v;
}

// ---------------- launch ----------------
extern "C" void kernel_launch(void* const* d_in, const int* in_sizes, int n_in,
                              void* d_out, int out_size){
    const float* g_i     = (const float*)d_in[0];
    const float* mention = (const float*)d_in[1];
    const float* dist_e  = (const float*)d_in[2];
    const float* genre_e = (const float*)d_in[3];
    const float* spk_e   = (const float*)d_in[4];
    const float* coarseW = (const float*)d_in[5];
    const float* W1      = (const float*)d_in[6];
    const float* b1      = (const float*)d_in[7];
    const float* W2      = (const float*)d_in[8];
    const float* b2      = (const float*)d_in[9];
    const float* Wf      = (const float*)d_in[10];
    const float* bfv     = (const float*)d_in[11];
    const int* starts    = (const int*)d_in[12];
    const int* ends      = (const int*)d_in[13];
    const int* gids      = (const int*)d_in[14];
    const int* sids      = (const int*)d_in[15];
    float* out = (float*)d_out;

    cudaFuncSetAttribute(bgemm, cudaFuncAttributeMaxDynamicSharedMemorySize, BG_SMEM);
    cudaFuncSetAttribute(mlp_bf, cudaFuncAttributeMaxDynamicSharedMemorySize, MLP_SMEM);

    // prep split into 3 so that user launch #4 (profiled by ncu -s 5) is the mode-6 bgemm
    prep_master<<<3072,256>>>(0,    g_i, coarseW, W1, Wf, b1, W2, dist_e, genre_e, spk_e); // 1
    prep_master<<<2304,256>>>(3072, g_i, coarseW, W1, Wf, b1, W2, dist_e, genre_e, spk_e); // 2
    prep_master<<<2084,256>>>(5376, g_i, coarseW, W1, Wf, b1, W2, dist_e, genre_e, spk_e); // 3
    bgemm<<<dim3(12, KSPAN/128),256,BG_SMEM>>>(6, d_gb, nullptr, GIDIM, nullptr, nullptr, gids);   // 4 <- profiled
    bgemm<<<dim3(KSPAN/128, KSPAN/128),256,BG_SMEM>>>(1, d_projb, d_gb, GIDIM, mention, nullptr, nullptr); // 5
    topk_kernel<<<KSPAN,512>>>();                                                          // 6
    build_A<<<MROWS/8,256>>>(0, starts, ends, sids);                                       // 7
    mlp_bf<<<dim3(NPAD/128, MROWS/128),256,MLP_SMEM>>>();                                  // 8
    reduce_sa<<<(MROWS+255)/256,256>>>();
    refine_kernel<<<KSPAN,128>>>(g_i, b2);
    build_gateA<<<(KSPAN*GIDIM+255)/256,256>>>(g_i);
    bgemm<<<dim3(GIDIM/128, KSPAN/128),256,BG_SMEM>>>(3, d_gateA, d_wft, KA, bfv, g_i, nullptr);
    // iteration 1
    bgemm<<<dim3(NPAD/128, KSPAN/128),256,BG_SMEM>>>(2, d_gnb, d_B1t, GIDIM, nullptr, nullptr, gids);
    build_A<<<MROWS/8,256>>>(1, starts, ends, sids);
    mlp_bf<<<dim3(NPAD/128, MROWS/128),256,MLP_SMEM>>>();
    reduce_sa<<<(MROWS+255)/256,256>>>();
    final_kernel<<<(KSPAN*(KANT+1)+255)/256,256>>>(b2, out);
}